// round 16
// baseline (speedup 1.0000x reference)
#include <cuda_runtime.h>

#define FULL 0xffffffffu

// ---------------- persistent scratch (self-resetting across replays) --------
__device__ float    g_F[8 * 81];        // grid evaluations of <Z_j>, [j][n]
__device__ unsigned g_ctr  = 0;         // producer warp-channels done (0..648)
__device__ unsigned g_done = 0;         // blocks done
__device__ float    g_partial[32] = {}; // per-batch dense accumulators

// producer barrier: warps 0-7 (threads 0..255)
#define BARP() asm volatile("bar.sync 1, 256;" ::: "memory")

#define CH 128
#define NP (CH + 3)    // 131 layer-1 values (halo)
#define NX (CH + 6)    // 134 x-sincos values

// per-axis Lagrange-trig dual basis from (cos a, sin a):
// L0=(1+c-s)/2, L1=s, L2=(1-c-s)/2 -> raw grid values are the coefficients
__device__ __forceinline__ void lag3(float cv, float sv, float* e) {
    e[0] = 0.5f * (1.f + cv - sv);
    e[1] = sv;
    e[2] = 0.5f * (1.f - cv - sv);
}

__global__ void __launch_bounds__(512) mega_kernel(const float* __restrict__ x,
                                                   const float* __restrict__ weights,
                                                   const float* __restrict__ dw,
                                                   const float* __restrict__ db,
                                                   float* __restrict__ out) {
    // producer state (blocks 0..80 only)
    __shared__ float2 psiA[256], psiB[256];
    __shared__ float  cw[24], sw[24];
    // consumer state (all blocks)
    __shared__ float coef[648];          // [ch][81] raw grid values
    __shared__ float xc[NX], xs[NX];     // sincos of input window
    __shared__ float ac[NP], as_[NP];    // sincos of layer-1 relu values
    __shared__ float red[16];

    int t = threadIdx.x;
    int lane = t & 31;
    int warp = t >> 5;
    int bid = blockIdx.x;                // 0..255
    int b  = bid >> 3;                   // batch 0..31
    int s0 = (bid & 7) * CH;             // layer-2 chunk start

    // ---- x-window sincos: warps 8-15 (threads 256..), overlap producers ----
    if (t >= 256) {
        int k = t - 256;
        if (k < NX) {
            int l = s0 - 2 + k;
            float cv = 1.f, sv = 0.f;
            if (l >= 0 && l < 1024) __sincosf(x[b * 1024 + l], &sv, &cv);
            xc[k] = cv; xs[k] = sv;
        }
    }

    // ---- producer: blocks 0..80, threads 0..255 = one amplitude each ----
    // index bit mapping: qubit q <-> bit (7-q) of amplitude index
    if (bid < 81 && t < 256) {
        if (t < 24) {
            const float TWO_PI = 6.28318530717958647692f;
            float w = weights[t];
            float wm = fmodf(w, TWO_PI);
            if (wm < 0.f) wm += TWO_PI;
            float sv, cv;
            __sincosf(0.5f * wm, &sv, &cv);
            cw[t] = cv;
            sw[t] = sv;
        }
        psiA[t] = make_float2((t == 0) ? 1.f : 0.f, 0.f);
        BARP();

        float2* cur = psiA;
        float2* nxt = psiB;

#pragma unroll 1
        for (int stage = 0; stage < 3; ++stage) {
            const float* cwp = &cw[stage * 8];
            const float* swp = &sw[stage * 8];
#pragma unroll 1
            for (int j = 0; j < 8; ++j) {
                float c = cwp[j], s = swp[j];
                int qm = 0x80 >> j;                    // qubit-j bit mask
                // RX(j): new = c*a - i*s*a[partner]
                {
                    float2 a = cur[t], o = cur[t ^ qm];
                    nxt[t] = make_float2(c * a.x + s * o.y, c * a.y - s * o.x);
                }
                BARP();
                { float2* tm = cur; cur = nxt; nxt = tm; }
                // W = CNOT·RY·CNOT
                {
                    int pm, sp;
                    if (j < 7) { pm = qm | (qm >> 1); sp = (t & qm) ? 1 : 0; }
                    else       { pm = 1;              sp = ((t >> 7) ^ t) & 1; }
                    float2 a = cur[t], o = cur[t ^ pm];
                    float sg = sp ? s : -s;
                    nxt[t] = make_float2(c * a.x + sg * o.x, c * a.y + sg * o.y);
                }
                BARP();
                { float2* tm = cur; cur = nxt; nxt = tm; }
                // RZ(j): diagonal, in place
                {
                    float f = (t & qm) ? s : -s;
                    float2 a = cur[t];
                    cur[t] = make_float2(c * a.x - f * a.y, c * a.y + f * a.x);
                }
                BARP();
            }
            if (stage == 0) {
                // data encoding RY at grid angles {0, pi/2, pi}
                const float GC[3] = {1.f, 0.70710678118654752440f, 0.f};
                const float GS[3] = {0.f, 0.70710678118654752440f, 1.f};
                int n = bid;
                int kk0 = n / 27, kk1 = (n / 9) % 3, kk2 = (n / 3) % 3, kk3 = n % 3;
                int ks[4] = {kk0, kk1, kk2, kk3};
#pragma unroll 1
                for (int q = 0; q < 4; ++q) {
                    float c = GC[ks[q]], s = GS[ks[q]];
                    int qm = 0x80 >> q;
                    float2 a = cur[t], o = cur[t ^ qm];
                    float sg = (t & qm) ? s : -s;
                    nxt[t] = make_float2(c * a.x + sg * o.x, c * a.y + sg * o.y);
                    BARP();
                    { float2* tm = cur; cur = nxt; nxt = tm; }
                }
            }
        }

        // probabilities -> nxt[].x
        {
            float2 a = cur[t];
            nxt[t].x = a.x * a.x + a.y * a.y;
        }
        BARP();
        // warp w reduces channel w: sign = bit (7-w) of index
        {
            int qm = 0x80 >> warp;
            float v = 0.f;
#pragma unroll
            for (int k = 0; k < 8; ++k) {
                int i = lane * 8 + k;
                float p = nxt[i].x;
                v += (i & qm) ? -p : p;
            }
#pragma unroll
            for (int o = 16; o; o >>= 1) v += __shfl_xor_sync(FULL, v, o);
            if (lane == 0) {
                g_F[warp * 81 + bid] = v;
                __threadfence();                 // my store visible before count
                atomicAdd(&g_ctr, 1u);
            }
        }
    }

    // ---- flag-sync: whole grid is resident (256 <= 296 capacity) ----
    if (t == 0) {
        volatile unsigned* pc = &g_ctr;
        while (*pc < 648u) __nanosleep(128);
        __threadfence();
    }
    __syncthreads();

    // ---- copy raw grid values (dual basis: no transform) ----
    for (int i = t; i < 648; i += 512) coef[i] = g_F[i];
    __syncthreads();

    // ---- layer 1: thread-per-position (p = s0 - 1 + t), t < NP ----
    if (t < NP) {
        int p = s0 - 1 + t;
        float cv = 1.f, sv = 0.f;            // OOB position -> angle 0
        if (p >= 0 && p < 1023) {
            float e0[3], e1[3], t23[9];
            lag3(xc[t], xs[t], e0);
            lag3(xc[t + 1], xs[t + 1], e1);
            {
                float e2[3], e3[3];
                lag3(xc[t + 2], xs[t + 2], e2);
                lag3(xc[t + 3], xs[t + 3], e3);
#pragma unroll
                for (int i = 0; i < 3; ++i)
#pragma unroll
                    for (int j = 0; j < 3; ++j) t23[i * 3 + j] = e2[i] * e3[j];
            }
            float v = 0.f;
#pragma unroll
            for (int i = 0; i < 9; ++i) {
                float pp = 0.f;
#pragma unroll
                for (int l = 0; l < 9; ++l) pp = fmaf(coef[i * 9 + l], t23[l], pp);
                v = fmaf(e0[i / 3] * e1[i % 3], pp, v);
            }
            __sincosf(fmaxf(v, 0.f), &sv, &cv);
        }
        ac[t] = cv; as_[t] = sv;
    }
    __syncthreads();

    // ---- layer 2: thread = (channel = t&7, 2 positions 2q/2q+1) ----
    int ch = t & 7;
    int q  = t >> 3;                     // 0..63 -> local positions 2q, 2q+1
    int pA = 2 * q, pB = 2 * q + 1;

    float e0a[3], e1a[3], e0b[3], e1b[3];
    lag3(ac[pA],     as_[pA],     e0a);
    lag3(ac[pA + 1], as_[pA + 1], e1a);
    lag3(ac[pB],     as_[pB],     e0b);
    lag3(ac[pB + 1], as_[pB + 1], e1b);

    float t23a[9], t23b[9];
    {
        float e2[3], e3[3];
        lag3(ac[pA + 2], as_[pA + 2], e2);
        lag3(ac[pA + 3], as_[pA + 3], e3);
#pragma unroll
        for (int i = 0; i < 3; ++i)
#pragma unroll
            for (int j = 0; j < 3; ++j) t23a[i * 3 + j] = e2[i] * e3[j];
        lag3(ac[pB + 2], as_[pB + 2], e2);
        lag3(ac[pB + 3], as_[pB + 3], e3);
#pragma unroll
        for (int i = 0; i < 3; ++i)
#pragma unroll
            for (int j = 0; j < 3; ++j) t23b[i * 3 + j] = e2[i] * e3[j];
    }

    const float* sc = &coef[ch * 81];
    float acc0 = 0.f, acc1 = 0.f;
#pragma unroll
    for (int i = 0; i < 9; ++i) {
        float pa = 0.f, pb = 0.f;
#pragma unroll
        for (int l = 0; l < 9; ++l) {
            float c = sc[i * 9 + l];     // one LDS feeds both positions
            pa = fmaf(c, t23a[l], pa);
            pb = fmaf(c, t23b[l], pb);
        }
        acc0 = fmaf(e0a[i / 3] * e1a[i % 3], pa, acc0);
        acc1 = fmaf(e0b[i / 3] * e1b[i % 3], pb, acc1);
    }

    // channel max across octet (warp-uniform shuffles)
    acc0 = fmaxf(acc0, __shfl_xor_sync(FULL, acc0, 1));
    acc0 = fmaxf(acc0, __shfl_xor_sync(FULL, acc0, 2));
    acc0 = fmaxf(acc0, __shfl_xor_sync(FULL, acc0, 4));
    acc1 = fmaxf(acc1, __shfl_xor_sync(FULL, acc1, 1));
    acc1 = fmaxf(acc1, __shfl_xor_sync(FULL, acc1, 2));
    acc1 = fmaxf(acc1, __shfl_xor_sync(FULL, acc1, 4));

    // dense contributions (relu(max) == max(relu))
    float contrib = 0.f;
    if (ch == 0) {
        int sA = s0 + pA, sB = s0 + pB;
        if (sA < 1022) contrib += fmaxf(acc0, 0.f) * dw[sA];
        if (sB < 1022) contrib += fmaxf(acc1, 0.f) * dw[sB];
    }
    contrib += __shfl_xor_sync(FULL, contrib, 8);
    contrib += __shfl_xor_sync(FULL, contrib, 16);
    if (lane == 0) red[warp] = contrib;
    __syncthreads();

    // ---- block total -> g_partial; last block finalizes + resets ----
    if (t == 0) {
        float r = 0.f;
#pragma unroll
        for (int w = 0; w < 16; ++w) r += red[w];
        atomicAdd(&g_partial[b], r);
        __threadfence();                        // partial visible before done++
        unsigned old = atomicAdd(&g_done, 1u);
        if (old == 255u) {                      // last block of this replay
            __threadfence();
            float bias = db[0];
#pragma unroll 4
            for (int bb = 0; bb < 32; ++bb) {
                float p = atomicAdd(&g_partial[bb], 0.f);   // coherent read
                out[bb] = p + bias;
                atomicExch(&g_partial[bb], 0.f);            // reset for replay
            }
            atomicExch(&g_ctr, 0u);
            atomicExch(&g_done, 0u);
            __threadfence();
        }
    }
}

// ---------------- launch ------------------------------------------------------
extern "C" void kernel_launch(void* const* d_in, const int* in_sizes, int n_in,
                              void* d_out, int out_size) {
    const float* x       = (const float*)d_in[0];   // (32,1024,1)
    const float* weights = (const float*)d_in[1];   // (3,8)
    const float* dw      = (const float*)d_in[2];   // (1022,1)
    const float* db      = (const float*)d_in[3];   // (1,)
    float* out = (float*)d_out;                     // (32,1)

    mega_kernel<<<256, 512>>>(x, weights, dw, db, out);
}

// round 17
// speedup vs baseline: 1.8664x; 1.8664x over previous
#include <cuda_runtime.h>

#define FULL 0xffffffffu

// ---------------- scratch ----------------------------------------------------
__device__ float g_F[8 * 81];     // grid evaluations of <Z_j>, layout [j][n]

// ---------------- warp statevector simulation (gridsim only) ----------------
struct St { float2 a[8]; };

__device__ __forceinline__ float2 shxor(float2 v, int m) {
    float2 r;
    r.x = __shfl_xor_sync(FULL, v.x, m);
    r.y = __shfl_xor_sync(FULL, v.y, m);
    return r;
}

template<int Q>
__device__ __forceinline__ void gateRY(St& st, float c, float s, int lane) {
    constexpr int lm = 1 << (4 - Q);
    float sg = (lane & lm) ? s : -s;
#pragma unroll
    for (int m = 0; m < 8; ++m) {
        float2 o = shxor(st.a[m], lm);
        float2 a = st.a[m];
        st.a[m] = make_float2(c * a.x + sg * o.x, c * a.y + sg * o.y);
    }
}

template<int Q>
__device__ __forceinline__ void gateRX(St& st, float c, float s, int lane) {
    if constexpr (Q >= 5) {
        constexpr int bit = 1 << (7 - Q);
#pragma unroll
        for (int m = 0; m < 8; ++m) {
            if ((m & bit) == 0) {
                float2 a = st.a[m], b = st.a[m | bit];
                st.a[m]       = make_float2(c * a.x + s * b.y, c * a.y - s * b.x);
                st.a[m | bit] = make_float2(c * b.x + s * a.y, c * b.y - s * a.x);
            }
        }
    } else {
        constexpr int lm = 1 << (4 - Q);
#pragma unroll
        for (int m = 0; m < 8; ++m) {
            float2 o = shxor(st.a[m], lm);
            float2 a = st.a[m];
            st.a[m] = make_float2(c * a.x + s * o.y, c * a.y - s * o.x);
        }
    }
}

template<int Q>
__device__ __forceinline__ void gateRZ(St& st, float c, float s, int lane) {
    if constexpr (Q >= 5) {
        constexpr int bit = 1 << (7 - Q);
#pragma unroll
        for (int m = 0; m < 8; ++m) {
            float f = (m & bit) ? s : -s;
            float2 a = st.a[m];
            st.a[m] = make_float2(c * a.x - f * a.y, c * a.y + f * a.x);
        }
    } else {
        constexpr int lm = 1 << (4 - Q);
        float f = (lane & lm) ? s : -s;
#pragma unroll
        for (int m = 0; m < 8; ++m) {
            float2 a = st.a[m];
            st.a[m] = make_float2(c * a.x - f * a.y, c * a.y + f * a.x);
        }
    }
}

// Fused CNOT·RY·CNOT (round-10 derivation)
template<int J>
__device__ __forceinline__ void fusedW(St& st, float c, float s, int lane) {
    if constexpr (J <= 3) {
        constexpr int cm = 1 << (4 - J);
        constexpr int tm = 1 << (3 - J);
        float sg = (lane & cm) ? s : -s;
#pragma unroll
        for (int m = 0; m < 8; ++m) {
            float2 o = shxor(st.a[m], cm | tm);
            float2 a = st.a[m];
            st.a[m] = make_float2(c * a.x + sg * o.x, c * a.y + sg * o.y);
        }
    } else if constexpr (J == 4) {
        float sg = (lane & 1) ? s : -s;
        float2 o[8];
#pragma unroll
        for (int m = 0; m < 8; ++m) o[m] = shxor(st.a[m ^ 4], 1);
#pragma unroll
        for (int m = 0; m < 8; ++m) {
            float2 a = st.a[m];
            st.a[m] = make_float2(c * a.x + sg * o[m].x, c * a.y + sg * o[m].y);
        }
    } else if constexpr (J == 5 || J == 6) {
        constexpr int cmask = (J == 5) ? 4 : 2;
        constexpr int xmask = (J == 5) ? 6 : 3;
        float2 old[8];
#pragma unroll
        for (int m = 0; m < 8; ++m) old[m] = st.a[m];
#pragma unroll
        for (int m = 0; m < 8; ++m) {
            float sg = (m & cmask) ? s : -s;
            st.a[m] = make_float2(c * old[m].x + sg * old[m ^ xmask].x,
                                  c * old[m].y + sg * old[m ^ xmask].y);
        }
    } else {
        int bc = (lane >> 4) & 1;
        float2 old[8];
#pragma unroll
        for (int m = 0; m < 8; ++m) old[m] = st.a[m];
#pragma unroll
        for (int m = 0; m < 8; ++m) {
            float sg = ((bc ^ (m & 1)) != 0) ? s : -s;
            st.a[m] = make_float2(c * old[m].x + sg * old[m ^ 1].x,
                                  c * old[m].y + sg * old[m ^ 1].y);
        }
    }
}

template<int J>
__device__ __forceinline__ void ansatzStep(St& st, const float* cw, const float* sw, int lane) {
    float c = cw[J], s = sw[J];
    gateRX<J>(st, c, s, lane);
    fusedW<J>(st, c, s, lane);
    gateRZ<J>(st, c, s, lane);
}

__device__ __forceinline__ void ansatz(St& st, const float* cw, const float* sw, int lane) {
    ansatzStep<0>(st, cw, sw, lane);
    ansatzStep<1>(st, cw, sw, lane);
    ansatzStep<2>(st, cw, sw, lane);
    ansatzStep<3>(st, cw, sw, lane);
    ansatzStep<4>(st, cw, sw, lane);
    ansatzStep<5>(st, cw, sw, lane);
    ansatzStep<6>(st, cw, sw, lane);
    ansatzStep<7>(st, cw, sw, lane);
}

// ---------------- kernel 1: 81 grid circuits ---------------------------------
__global__ void gridsim_kernel(const float* __restrict__ weights,
                               const float* __restrict__ db,
                               float* __restrict__ out) {
    __shared__ float cw[24], sw[24];
    int lane = threadIdx.x;

    if (blockIdx.x == 0) out[lane] = db[0];   // seed output with bias

    if (lane < 24) {
        const float TWO_PI = 6.28318530717958647692f;
        float w = weights[lane];
        float wm = fmodf(w, TWO_PI);
        if (wm < 0.f) wm += TWO_PI;
        float sv, cv;
        __sincosf(0.5f * wm, &sv, &cv);
        cw[lane] = cv;
        sw[lane] = sv;
    }
    __syncwarp();

    St st;
#pragma unroll
    for (int m = 0; m < 8; ++m) st.a[m] = make_float2(0.f, 0.f);
    if (lane == 0) st.a[0] = make_float2(1.f, 0.f);
    ansatz(st, &cw[0], &sw[0], lane);

    const float GC[3] = {1.f, 0.70710678118654752440f, 0.f};
    const float GS[3] = {0.f, 0.70710678118654752440f, 1.f};
    int n = blockIdx.x;
    int k0 = n / 27, k1 = (n / 9) % 3, k2 = (n / 3) % 3, k3 = n % 3;
    gateRY<0>(st, GC[k0], GS[k0], lane);
    gateRY<1>(st, GC[k1], GS[k1], lane);
    gateRY<2>(st, GC[k2], GS[k2], lane);
    gateRY<3>(st, GC[k3], GS[k3], lane);

    ansatz(st, &cw[8],  &sw[8],  lane);
    ansatz(st, &cw[16], &sw[16], lane);

    float vj[8];
#pragma unroll
    for (int j = 0; j < 8; ++j) vj[j] = 0.f;
#pragma unroll
    for (int m = 0; m < 8; ++m) {
        float2 a = st.a[m];
        float p = a.x * a.x + a.y * a.y;
        int idx = (lane << 3) | m;
#pragma unroll
        for (int j = 0; j < 8; ++j) vj[j] += ((idx >> (7 - j)) & 1) ? -p : p;
    }
#pragma unroll
    for (int j = 0; j < 8; ++j) {
#pragma unroll
        for (int o = 16; o; o >>= 1) vj[j] += __shfl_xor_sync(FULL, vj[j], o);
    }
    if (lane == 0) {
#pragma unroll
        for (int j = 0; j < 8; ++j) g_F[j * 81 + n] = vj[j];
    }
}

// ---------------- kernel 2: layer1 + layer2 + pool + dense (dual basis) -----
// 512 threads; CH = 128 layer-2 positions per block; grid (8, 32).
// L1 split across warp halves; L2 reads shared per-position factors from smem.
#define CH 128
#define NP (CH + 3)    // 131 layer-1 values (halo)
#define NX (CH + 6)    // 134 x-sincos values

// per-axis Lagrange-trig dual basis from (cos a, sin a):
// L0=(1+c-s)/2, L1=s, L2=(1-c-s)/2 -> raw grid values are the coefficients
__device__ __forceinline__ void lag3(float cv, float sv, float* e) {
    e[0] = 0.5f * (1.f + cv - sv);
    e[1] = sv;
    e[2] = 0.5f * (1.f - cv - sv);
}

__global__ void __launch_bounds__(512) fused_kernel(const float* __restrict__ x,
                                                    const float* __restrict__ dw,
                                                    float* __restrict__ out) {
    __shared__ float coef[648];          // [ch][81] raw grid values
    __shared__ float xc[NX], xs[NX];     // sincos of input window
    __shared__ float ac[NP], as_[NP];    // sincos of layer-1 relu values
    __shared__ float vh[NP];             // L1 upper-half partial sums
    __shared__ float fct[CH * 15];       // per-L2-position factors: e0[3],e1[3],t23[9]
    __shared__ float red[16];

    int t = threadIdx.x;
    int lane = t & 31;
    int warp = t >> 5;
    int b = blockIdx.y;
    int s0 = blockIdx.x * CH;

    // --- straight copy (g_F already [j][81]) ---
    for (int i = t; i < 648; i += 512) coef[i] = g_F[i];
    // --- sincos of x window: x index l = s0-2+k ---
    if (t < NX) {
        int l = s0 - 2 + t;
        float cv = 1.f, sv = 0.f;
        if (l >= 0 && l < 1024) __sincosf(x[b * 1024 + l], &sv, &cv);
        xc[t] = cv; xs[t] = sv;
    }
    __syncthreads();

    // --- layer 1, pass A: warp-uniform half split (h = t>>8, k = t&255) ---
    // h=0 warps do i-terms 0..3, h=1 warps do i-terms 4..8 for position k.
    int h = t >> 8;            // 0 for warps 0-7, 1 for warps 8-15
    int k = t & 255;           // position index (valid when k < NP)
    {
        int kc = (k < NP) ? k : 0;
        float e0[3], e1[3], t23[9];
        lag3(xc[kc], xs[kc], e0);
        lag3(xc[kc + 1], xs[kc + 1], e1);
        {
            float e2[3], e3[3];
            lag3(xc[kc + 2], xs[kc + 2], e2);
            lag3(xc[kc + 3], xs[kc + 3], e3);
#pragma unroll
            for (int i = 0; i < 3; ++i)
#pragma unroll
                for (int j = 0; j < 3; ++j) t23[i * 3 + j] = e2[i] * e3[j];
        }
        float v = 0.f;
        if (h == 0) {
#pragma unroll
            for (int i = 0; i < 4; ++i) {
                float pp = 0.f;
#pragma unroll
                for (int l = 0; l < 9; ++l) pp = fmaf(coef[i * 9 + l], t23[l], pp);
                v = fmaf(e0[i / 3] * e1[i % 3], pp, v);
            }
            if (k < NP) vh[k] = v;           // reuse vh for lower half too
        } else {
#pragma unroll
            for (int i = 4; i < 9; ++i) {
                float pp = 0.f;
#pragma unroll
                for (int l = 0; l < 9; ++l) pp = fmaf(coef[i * 9 + l], t23[l], pp);
                v = fmaf(e0[i / 3] * e1[i % 3], pp, v);
            }
            // upper half written after lower half's store: use separate slot
            if (k < NP) as_[k] = v;          // as_ temporarily holds upper part
        }
    }
    __syncthreads();

    // --- layer 1, pass B: finalize (threads k < NP, h == 0 warps) ---
    if (h == 0 && k < NP) {
        int p = s0 - 1 + k;
        float cv = 1.f, sv = 0.f;            // OOB position -> angle 0
        if (p >= 0 && p < 1023) {
            float v = vh[k] + as_[k];
            __sincosf(fmaxf(v, 0.f), &sv, &cv);
        }
        ac[k] = cv; vh[k] = sv;              // vh now holds sin values
    }
    __syncthreads();

    // --- factor phase: per-L2-position factors into fct[pos*15 + c] ---
    if (t < CH) {
        float e[3];
        float* f = &fct[t * 15];
        lag3(ac[t], vh[t], e);
        f[0] = e[0]; f[1] = e[1]; f[2] = e[2];
        lag3(ac[t + 1], vh[t + 1], e);
        f[3] = e[0]; f[4] = e[1]; f[5] = e[2];
        float e2[3], e3[3];
        lag3(ac[t + 2], vh[t + 2], e2);
        lag3(ac[t + 3], vh[t + 3], e3);
#pragma unroll
        for (int i = 0; i < 3; ++i)
#pragma unroll
            for (int j = 0; j < 3; ++j) f[6 + i * 3 + j] = e2[i] * e3[j];
    }
    __syncthreads();

    // --- layer 2: thread = (channel = t&7, 2 positions 2q/2q+1) ---
    int ch = t & 7;
    int q  = t >> 3;                     // 0..63 -> local positions 2q, 2q+1
    int pA = 2 * q, pB = 2 * q + 1;
    const float* fa = &fct[pA * 15];
    const float* fb = &fct[pB * 15];

    float t23a[9], t23b[9];
#pragma unroll
    for (int l = 0; l < 9; ++l) { t23a[l] = fa[6 + l]; t23b[l] = fb[6 + l]; }

    const float* sc = &coef[ch * 81];
    float acc0 = 0.f, acc1 = 0.f;
#pragma unroll
    for (int i = 0; i < 9; ++i) {
        float pa = 0.f, pb = 0.f;
#pragma unroll
        for (int l = 0; l < 9; ++l) {
            float c = sc[i * 9 + l];     // one LDS feeds both positions
            pa = fmaf(c, t23a[l], pa);
            pb = fmaf(c, t23b[l], pb);
        }
        float ea = fa[i / 3] * fa[3 + i % 3];   // octet-broadcast LDS
        float eb = fb[i / 3] * fb[3 + i % 3];
        acc0 = fmaf(ea, pa, acc0);
        acc1 = fmaf(eb, pb, acc1);
    }

    // channel max across octet (warp-uniform shuffles)
    acc0 = fmaxf(acc0, __shfl_xor_sync(FULL, acc0, 1));
    acc0 = fmaxf(acc0, __shfl_xor_sync(FULL, acc0, 2));
    acc0 = fmaxf(acc0, __shfl_xor_sync(FULL, acc0, 4));
    acc1 = fmaxf(acc1, __shfl_xor_sync(FULL, acc1, 1));
    acc1 = fmaxf(acc1, __shfl_xor_sync(FULL, acc1, 2));
    acc1 = fmaxf(acc1, __shfl_xor_sync(FULL, acc1, 4));

    // dense contributions (relu(max) == max(relu))
    float contrib = 0.f;
    if (ch == 0) {
        int sA = s0 + pA, sB = s0 + pB;
        if (sA < 1022) contrib += fmaxf(acc0, 0.f) * dw[sA];
        if (sB < 1022) contrib += fmaxf(acc1, 0.f) * dw[sB];
    }
    contrib += __shfl_xor_sync(FULL, contrib, 8);
    contrib += __shfl_xor_sync(FULL, contrib, 16);
    if (lane == 0) red[warp] = contrib;
    __syncthreads();
    if (warp == 0) {
        float r = (lane < 16) ? red[lane] : 0.f;
        r += __shfl_xor_sync(FULL, r, 1);
        r += __shfl_xor_sync(FULL, r, 2);
        r += __shfl_xor_sync(FULL, r, 4);
        r += __shfl_xor_sync(FULL, r, 8);
        if (lane == 0) atomicAdd(&out[b], r);
    }
}

// ---------------- launch ------------------------------------------------------
extern "C" void kernel_launch(void* const* d_in, const int* in_sizes, int n_in,
                              void* d_out, int out_size) {
    const float* x       = (const float*)d_in[0];   // (32,1024,1)
    const float* weights = (const float*)d_in[1];   // (3,8)
    const float* dw      = (const float*)d_in[2];   // (1022,1)
    const float* db      = (const float*)d_in[3];   // (1,)
    float* out = (float*)d_out;                     // (32,1)

    gridsim_kernel<<<81, 32>>>(weights, db, out);
    dim3 g((1022 + CH - 1) / CH, 32);               // (8, 32)
    fused_kernel<<<g, 512>>>(x, dw, out);
}